// round 4
// baseline (speedup 1.0000x reference)
#include <cuda_runtime.h>
#include <cuda_bf16.h>
#include <cstdint>

#define BB 2
#define TT 4096
#define CDIM 768
#define HH 12
#define DD 64
#define BT (BB*TT)   // 8192

// Scratch (allocation-free rule: __device__ globals)
// q/k/v hold tf32 bit patterns (written by projection GEMMs); ctx is f32.
__device__ float g_q[BT*CDIM];
__device__ float g_k[BT*CDIM];
__device__ float g_v[BT*CDIM];
__device__ float g_ctx[BT*CDIM];

// ---------------------------------------------------------------------------
// helpers
// ---------------------------------------------------------------------------
__device__ __forceinline__ unsigned f2tf(float f) {
    unsigned u;
    asm("cvt.rna.tf32.f32 %0, %1;" : "=r"(u) : "f"(f));
    return u;
}

__device__ __forceinline__ void mma_tf32(float c[4], const unsigned a[4],
                                         const unsigned b[2]) {
    asm volatile(
        "mma.sync.aligned.m16n8k8.row.col.f32.tf32.tf32.f32 "
        "{%0,%1,%2,%3}, {%4,%5,%6,%7}, {%8,%9}, {%0,%1,%2,%3};\n"
        : "+f"(c[0]), "+f"(c[1]), "+f"(c[2]), "+f"(c[3])
        : "r"(a[0]), "r"(a[1]), "r"(a[2]), "r"(a[3]),
          "r"(b[0]), "r"(b[1]));
}

__device__ __forceinline__ void cp_async16(uint32_t saddr, const void* gptr) {
    asm volatile("cp.async.cg.shared.global [%0], [%1], 16;"
                 :: "r"(saddr), "l"(gptr));
}
__device__ __forceinline__ void cp_async_commit() {
    asm volatile("cp.async.commit_group;");
}
__device__ __forceinline__ void cp_async_wait0() {
    asm volatile("cp.async.wait_group 0;");
}
__device__ __forceinline__ void cp_async_wait1() {
    asm volatile("cp.async.wait_group 1;");
}

// ---------------------------------------------------------------------------
// GEMM: Y[M,N] = X[M,K] * W[N,K]^T,  M=8192, N=K=768  (unchanged this round)
// ---------------------------------------------------------------------------
template <bool TF32_OUT>
__global__ __launch_bounds__(256) void gemm_mma_kernel(
    const float* __restrict__ X, const float* __restrict__ W,
    float* __restrict__ Y, float out_scale) {
    __shared__ unsigned As[128][36];
    __shared__ unsigned Bs[128][36];

    const int tid  = threadIdx.x;
    const int warp = tid >> 5;
    const int lane = tid & 31;
    const int gid  = lane >> 2;   // 0..7
    const int tig  = lane & 3;    // 0..3
    const int wm   = warp >> 2;   // 0..1
    const int wn   = warp & 3;    // 0..3

    const int m0 = blockIdx.y * 128;
    const int n0 = blockIdx.x * 128;

    const int lrow = tid >> 3;         // 0..31
    const int lcol = (tid & 7) * 4;    // 0..28

    float c[4][4][4];
#pragma unroll
    for (int mt = 0; mt < 4; mt++)
#pragma unroll
        for (int nt = 0; nt < 4; nt++)
#pragma unroll
            for (int i = 0; i < 4; i++) c[mt][nt][i] = 0.f;

    for (int k0 = 0; k0 < CDIM; k0 += 32) {
        float4 xa[4], wb[4];
#pragma unroll
        for (int i = 0; i < 4; i++) {
            xa[i] = *(const float4*)&X[(size_t)(m0 + lrow + i * 32) * CDIM + k0 + lcol];
            wb[i] = *(const float4*)&W[(size_t)(n0 + lrow + i * 32) * CDIM + k0 + lcol];
        }
        __syncthreads();
#pragma unroll
        for (int i = 0; i < 4; i++) {
            uint4 xu, wu;
            xu.x = f2tf(xa[i].x); xu.y = f2tf(xa[i].y);
            xu.z = f2tf(xa[i].z); xu.w = f2tf(xa[i].w);
            wu.x = f2tf(wb[i].x); wu.y = f2tf(wb[i].y);
            wu.z = f2tf(wb[i].z); wu.w = f2tf(wb[i].w);
            *(uint4*)&As[lrow + i * 32][lcol] = xu;
            *(uint4*)&Bs[lrow + i * 32][lcol] = wu;
        }
        __syncthreads();

#pragma unroll
        for (int ks = 0; ks < 4; ks++) {
            const int kb = ks * 8;
            unsigned a[4][4], b[4][2];
#pragma unroll
            for (int mt = 0; mt < 4; mt++) {
                const int r = wm * 64 + mt * 16 + gid;
                a[mt][0] = As[r][kb + tig];
                a[mt][1] = As[r + 8][kb + tig];
                a[mt][2] = As[r][kb + tig + 4];
                a[mt][3] = As[r + 8][kb + tig + 4];
            }
#pragma unroll
            for (int nt = 0; nt < 4; nt++) {
                const int rn = wn * 32 + nt * 8 + gid;
                b[nt][0] = Bs[rn][kb + tig];
                b[nt][1] = Bs[rn][kb + tig + 4];
            }
#pragma unroll
            for (int mt = 0; mt < 4; mt++)
#pragma unroll
                for (int nt = 0; nt < 4; nt++)
                    mma_tf32(c[mt][nt], a[mt], b[nt]);
        }
    }

#pragma unroll
    for (int mt = 0; mt < 4; mt++) {
        const int r = m0 + wm * 64 + mt * 16 + gid;
#pragma unroll
        for (int nt = 0; nt < 4; nt++) {
            const int cn = n0 + wn * 32 + nt * 8 + 2 * tig;
            if (TF32_OUT) {
                uint2 o01 = make_uint2(f2tf(c[mt][nt][0] * out_scale),
                                       f2tf(c[mt][nt][1] * out_scale));
                uint2 o23 = make_uint2(f2tf(c[mt][nt][2] * out_scale),
                                       f2tf(c[mt][nt][3] * out_scale));
                *(uint2*)&Y[(size_t)r * CDIM + cn]       = o01;
                *(uint2*)&Y[(size_t)(r + 8) * CDIM + cn] = o23;
            } else {
                *(float2*)&Y[(size_t)r * CDIM + cn] =
                    make_float2(c[mt][nt][0], c[mt][nt][1]);
                *(float2*)&Y[(size_t)(r + 8) * CDIM + cn] =
                    make_float2(c[mt][nt][2], c[mt][nt][3]);
            }
        }
    }
}

// ---------------------------------------------------------------------------
// Flash attention (causal), tf32 mma, online softmax — SW-PIPELINED.
// K double-buffered (prefetch 1 iter ahead), V issued at iter start and
// awaited just before PV. Q smem reused as P buffer after fragment extract.
// smem = 64*(68*3 + 72) words = 69KB -> 3 blocks/SM.
// cp.async group discipline (per-thread FIFO):
//   prologue: commit {Q}, commit {K0}; wait1 -> Q done.
//   iter jt : wait0 -> K[jt] done; sync; commit {V[jt]}; commit {K[jt+1]};
//             S+softmax; (jt<qt ? wait1 : wait0) -> V[jt] done; sync; PV.
// ---------------------------------------------------------------------------
#define KROW 68
#define VROW 72
#define ATTN_SMEM ((3 * 64 * KROW + 64 * VROW) * 4)

__global__ __launch_bounds__(128) void attn_mma_kernel(
    const float* __restrict__ q, const float* __restrict__ k,
    const float* __restrict__ v, float* __restrict__ ctx) {
    extern __shared__ unsigned sm[];
    unsigned* QPs = sm;                  // Q tile, then P tile
    unsigned* Ks0 = sm + 64 * KROW;
    unsigned* Ks1 = sm + 2 * 64 * KROW;
    unsigned* Vs  = sm + 3 * 64 * KROW;

    const int tid  = threadIdx.x;
    const int warp = tid >> 5;
    const int lane = tid & 31;
    const int gid  = lane >> 2;
    const int tig  = lane & 3;
    const int rw   = warp * 16 + gid;    // this thread's first local row

    const int qt = gridDim.x - 1 - blockIdx.x;   // long blocks first
    const int h  = blockIdx.y;
    const int b  = blockIdx.z;
    const int q0 = qt * 64;

    const uint32_t qp_base = (uint32_t)__cvta_generic_to_shared(QPs);
    const uint32_t k0_base = (uint32_t)__cvta_generic_to_shared(Ks0);
    const uint32_t k1_base = (uint32_t)__cvta_generic_to_shared(Ks1);
    const uint32_t vs_base = (uint32_t)__cvta_generic_to_shared(Vs);

    const int lrr = tid >> 4;            // 0..7   (row group for loads)
    const int lc4 = (tid & 15) * 4;      // 0..60  (col for loads)
    const size_t hoff = (size_t)h * DD + lc4;

    // ---- prologue: Q load || K[0] prefetch ----
#pragma unroll
    for (int i = 0; i < 8; i++) {
        int rr = lrr + i * 8;
        cp_async16(qp_base + (rr * KROW + lc4) * 4,
                   &q[(size_t)(b * TT + q0 + rr) * CDIM + hoff]);
    }
    cp_async_commit();
#pragma unroll
    for (int i = 0; i < 8; i++) {
        int rr = lrr + i * 8;
        cp_async16(k0_base + (rr * KROW + lc4) * 4,
                   &k[(size_t)(b * TT + rr) * CDIM + hoff]);
    }
    cp_async_commit();
    cp_async_wait1();        // Q arrived; K[0] may still fly
    __syncthreads();

    // Q fragments (held in registers for the whole q-tile)
    unsigned qa[8][4];
#pragma unroll
    for (int ks = 0; ks < 8; ks++) {
        qa[ks][0] = QPs[rw * KROW + ks * 8 + tig];
        qa[ks][1] = QPs[(rw + 8) * KROW + ks * 8 + tig];
        qa[ks][2] = QPs[rw * KROW + ks * 8 + tig + 4];
        qa[ks][3] = QPs[(rw + 8) * KROW + ks * 8 + tig + 4];
    }

    float o[8][4];
#pragma unroll
    for (int nt = 0; nt < 8; nt++)
#pragma unroll
        for (int i = 0; i < 4; i++) o[nt][i] = 0.f;
    float m0r = -1e30f, m1r = -1e30f, l0 = 0.f, l1 = 0.f;

    for (int jt = 0; jt <= qt; jt++) {
        const unsigned* Kc = (jt & 1) ? Ks1 : Ks0;
        const uint32_t knext = (jt & 1) ? k0_base : k1_base;

        cp_async_wait0();     // K[jt] fully arrived (this thread's groups)
        __syncthreads();      // K visible to all; Vs + prev K buffer free

        // issue V[jt]  (group A)
#pragma unroll
        for (int i = 0; i < 8; i++) {
            int rr = lrr + i * 8;
            cp_async16(vs_base + (rr * VROW + lc4) * 4,
                       &v[(size_t)(b * TT + jt * 64 + rr) * CDIM + hoff]);
        }
        cp_async_commit();
        // prefetch K[jt+1] (group B)
        if (jt < qt) {
#pragma unroll
            for (int i = 0; i < 8; i++) {
                int rr = lrr + i * 8;
                cp_async16(knext + (rr * KROW + lc4) * 4,
                           &k[(size_t)(b * TT + (jt + 1) * 64 + rr) * CDIM + hoff]);
            }
            cp_async_commit();
        }

        // S = Q K^T  (16 x 64 per warp)
        float s[8][4];
#pragma unroll
        for (int nt = 0; nt < 8; nt++)
#pragma unroll
            for (int i = 0; i < 4; i++) s[nt][i] = 0.f;

#pragma unroll
        for (int ks = 0; ks < 8; ks++) {
            const int kb = ks * 8;
#pragma unroll
            for (int nt = 0; nt < 8; nt++) {
                unsigned bb[2];
                const int rn = nt * 8 + gid;
                bb[0] = Kc[rn * KROW + kb + tig];
                bb[1] = Kc[rn * KROW + kb + tig + 4];
                mma_tf32(s[nt], qa[ks], bb);
            }
        }

        // causal mask (diagonal tile only)
        if (jt == qt) {
#pragma unroll
            for (int nt = 0; nt < 8; nt++) {
                const int cg = nt * 8 + 2 * tig;
                if (cg > rw)         s[nt][0] = -1e30f;
                if (cg + 1 > rw)     s[nt][1] = -1e30f;
                if (cg > rw + 8)     s[nt][2] = -1e30f;
                if (cg + 1 > rw + 8) s[nt][3] = -1e30f;
            }
        }

        // row maxima (two rows per thread)
        float mx0 = -1e30f, mx1 = -1e30f;
#pragma unroll
        for (int nt = 0; nt < 8; nt++) {
            mx0 = fmaxf(mx0, fmaxf(s[nt][0], s[nt][1]));
            mx1 = fmaxf(mx1, fmaxf(s[nt][2], s[nt][3]));
        }
        mx0 = fmaxf(mx0, __shfl_xor_sync(0xffffffffu, mx0, 1));
        mx0 = fmaxf(mx0, __shfl_xor_sync(0xffffffffu, mx0, 2));
        mx1 = fmaxf(mx1, __shfl_xor_sync(0xffffffffu, mx1, 1));
        mx1 = fmaxf(mx1, __shfl_xor_sync(0xffffffffu, mx1, 2));

        const float mn0 = fmaxf(m0r, mx0);
        const float mn1 = fmaxf(m1r, mx1);
        const float a0 = __expf(m0r - mn0);
        const float a1 = __expf(m1r - mn1);

        float ls0 = 0.f, ls1 = 0.f;
#pragma unroll
        for (int nt = 0; nt < 8; nt++) {
            s[nt][0] = __expf(s[nt][0] - mn0); ls0 += s[nt][0];
            s[nt][1] = __expf(s[nt][1] - mn0); ls0 += s[nt][1];
            s[nt][2] = __expf(s[nt][2] - mn1); ls1 += s[nt][2];
            s[nt][3] = __expf(s[nt][3] - mn1); ls1 += s[nt][3];
        }
        ls0 += __shfl_xor_sync(0xffffffffu, ls0, 1);
        ls0 += __shfl_xor_sync(0xffffffffu, ls0, 2);
        ls1 += __shfl_xor_sync(0xffffffffu, ls1, 1);
        ls1 += __shfl_xor_sync(0xffffffffu, ls1, 2);

        l0 = l0 * a0 + ls0; m0r = mn0;
        l1 = l1 * a1 + ls1; m1r = mn1;
#pragma unroll
        for (int nt = 0; nt < 8; nt++) {
            o[nt][0] *= a0; o[nt][1] *= a0;
            o[nt][2] *= a1; o[nt][3] *= a1;
        }

        // P -> smem as tf32 (warp-private 16-row band: __syncwarp only)
#pragma unroll
        for (int nt = 0; nt < 8; nt++) {
            const int cc = nt * 8 + 2 * tig;
            *(uint2*)&QPs[rw * KROW + cc] =
                make_uint2(f2tf(s[nt][0]), f2tf(s[nt][1]));
            *(uint2*)&QPs[(rw + 8) * KROW + cc] =
                make_uint2(f2tf(s[nt][2]), f2tf(s[nt][3]));
        }
        __syncwarp();

        // V[jt] retired (K[jt+1] may remain in flight)
        if (jt < qt) cp_async_wait1(); else cp_async_wait0();
        __syncthreads();      // V visible to all

        // O += P V  (16 x 64 per warp)
#pragma unroll
        for (int kc = 0; kc < 8; kc++) {
            const int kb = kc * 8;
            unsigned pa[4];
            pa[0] = QPs[rw * KROW + kb + tig];
            pa[1] = QPs[(rw + 8) * KROW + kb + tig];
            pa[2] = QPs[rw * KROW + kb + tig + 4];
            pa[3] = QPs[(rw + 8) * KROW + kb + tig + 4];
#pragma unroll
            for (int nt = 0; nt < 8; nt++) {
                unsigned bb[2];
                bb[0] = Vs[(kb + tig) * VROW + nt * 8 + gid];
                bb[1] = Vs[(kb + tig + 4) * VROW + nt * 8 + gid];
                mma_tf32(o[nt], pa, bb);
            }
        }
    }

    // epilogue (f32 out)
    const float inv0 = 1.f / l0;
    const float inv1 = 1.f / l1;
    const size_t r0 = (size_t)(b * TT + q0 + rw) * CDIM + h * DD;
    const size_t r1 = (size_t)(b * TT + q0 + rw + 8) * CDIM + h * DD;
#pragma unroll
    for (int nt = 0; nt < 8; nt++) {
        const int cc = nt * 8 + 2 * tig;
        *(float2*)&ctx[r0 + cc] = make_float2(o[nt][0] * inv0, o[nt][1] * inv0);
        *(float2*)&ctx[r1 + cc] = make_float2(o[nt][2] * inv1, o[nt][3] * inv1);
    }
}

// ---------------------------------------------------------------------------
extern "C" void kernel_launch(void* const* d_in, const int* in_sizes, int n_in,
                              void* d_out, int out_size) {
    const float* x  = (const float*)d_in[0];
    const float* wq = (const float*)d_in[1];
    const float* wk = (const float*)d_in[2];
    const float* wv = (const float*)d_in[3];
    const float* wo = (const float*)d_in[4];
    float* out = (float*)d_out;

    float* q;   cudaGetSymbolAddress((void**)&q,   g_q);
    float* kk;  cudaGetSymbolAddress((void**)&kk,  g_k);
    float* v;   cudaGetSymbolAddress((void**)&v,   g_v);
    float* ctx; cudaGetSymbolAddress((void**)&ctx, g_ctx);

    cudaFuncSetAttribute(attn_mma_kernel,
                         cudaFuncAttributeMaxDynamicSharedMemorySize, ATTN_SMEM);

    dim3 gg(CDIM / 128, BT / 128);
    // Q pre-scaled by 1/sqrt(D), written as tf32 bits
    gemm_mma_kernel<true><<<gg, 256>>>(x, wq, q, 0.125f);
    gemm_mma_kernel<true><<<gg, 256>>>(x, wk, kk, 1.0f);
    gemm_mma_kernel<true><<<gg, 256>>>(x, wv, v, 1.0f);

    dim3 ga(TT / 64, HH, BB);
    attn_mma_kernel<<<ga, 128, ATTN_SMEM>>>(q, kk, v, ctx);

    gemm_mma_kernel<false><<<gg, 256>>>(ctx, wo, out, 1.0f);
}